// round 14
// baseline (speedup 1.0000x reference)
#include <cuda_runtime.h>
#include <cuda_bf16.h>
#include <math.h>
#include <cstdint>

#define N_NODES_MAX 200000
#define N_QUERY_MAX 131072
#define FEAT 9
#define HID 64
#define OUT 128

typedef unsigned long long ull;

// ---------------- static device scratch ----------------
__device__ float4 g_geom4[N_NODES_MAX];
__device__ float  g_feat[FEAT * N_QUERY_MAX];   // column-major [FEAT][Q]
__device__ double g_sums[2 * FEAT];

// ---------------- f32x2 helpers ----------------
__device__ __forceinline__ ull pk2(float lo, float hi) {
    ull r; asm("mov.b64 %0,{%1,%2};" : "=l"(r) : "f"(lo), "f"(hi)); return r;
}
__device__ __forceinline__ void upk2(float& lo, float& hi, ull v) {
    asm("mov.b64 {%0,%1},%2;" : "=f"(lo), "=f"(hi) : "l"(v));
}
__device__ __forceinline__ ull fma2(ull a, ull b, ull c) {
    ull d; asm("fma.rn.f32x2 %0,%1,%2,%3;" : "=l"(d) : "l"(a), "l"(b), "l"(c));
    return d;
}

// bf16 mma (arch-generic PTX, works on compute_103)
__device__ __forceinline__ void mma16816(float* d,
                                         uint32_t a0, uint32_t a1, uint32_t a2, uint32_t a3,
                                         uint32_t b0, uint32_t b1) {
    asm volatile(
        "mma.sync.aligned.m16n8k16.row.col.f32.bf16.bf16.f32 "
        "{%0,%1,%2,%3},{%4,%5,%6,%7},{%8,%9},{%0,%1,%2,%3};"
        : "+f"(d[0]), "+f"(d[1]), "+f"(d[2]), "+f"(d[3])
        : "r"(a0), "r"(a1), "r"(a2), "r"(a3), "r"(b0), "r"(b1));
}

__device__ __forceinline__ uint32_t bf2pack(float v0, float v1) {
    __nv_bfloat16 b0 = __float2bfloat16(v0);
    __nv_bfloat16 b1 = __float2bfloat16(v1);
    uint16_t u0, u1;
    memcpy(&u0, &b0, 2); memcpy(&u1, &b1, 2);
    return (uint32_t)u0 | ((uint32_t)u1 << 16);
}

// ---------------- K1: pad geometry + zero accumulators ----------------
__global__ void prep_kernel(const float* __restrict__ geom, int n) {
    int i = blockIdx.x * blockDim.x + threadIdx.x;
    if (blockIdx.x == 0 && threadIdx.x < 2 * FEAT) g_sums[threadIdx.x] = 0.0;
    if (i < n) {
        float4 p;
        p.x = geom[3 * i + 0];
        p.y = geom[3 * i + 1];
        p.z = geom[3 * i + 2];
        p.w = 0.f;
        g_geom4[i] = p;
    }
}

__global__ void dummy_kernel() {}

// ---------------- K2: moments + features, 4 threads per query (R10 best) ----------------
__global__ __launch_bounds__(256)
void moments_feat_kernel(const float* __restrict__ lq,
                         const int* __restrict__ nidx,
                         const int* __restrict__ rs,
                         int Qn) {
    int t = blockIdx.x * blockDim.x + threadIdx.x;
    int q = t >> 2;
    int sub = t & 3;
    bool valid = (q < Qn);
    int qc = valid ? q : (Qn - 1);

    int start = rs[qc];
    int end   = rs[qc + 1];
    int cnt   = end - start;

    float qx = __ldg(&lq[3 * qc + 0]);
    float qy = __ldg(&lq[3 * qc + 1]);
    float qz = __ldg(&lq[3 * qc + 2]);

    float sd = 0.f, sd2 = 0.f;
    float sx = 0.f, sy = 0.f, sz = 0.f;
    float sxx = 0.f, sxy = 0.f, sxz = 0.f, syy = 0.f, syz = 0.f, szz = 0.f;

    if (cnt == 32 && (start & 3) == 0) {
        const int4* ip = (const int4*)(nidx + start) + sub * 2;
        int4 a = __ldg(ip), b = __ldg(ip + 1);
        int idf[8] = {a.x, a.y, a.z, a.w, b.x, b.y, b.z, b.w};
#pragma unroll
        for (int e = 0; e < 8; e++) {
            float4 p = g_geom4[idf[e]];
            float dx = p.x - qx, dy = p.y - qy, dz = p.z - qz;
            float d2 = dx * dx + dy * dy + dz * dz;
            sd  += sqrtf(d2);
            sd2 += d2;
            sx += p.x; sy += p.y; sz += p.z;
            sxx += p.x * p.x; sxy += p.x * p.y; sxz += p.x * p.z;
            syy += p.y * p.y; syz += p.y * p.z; szz += p.z * p.z;
        }
    } else {
        for (int e = start + sub; e < end; e += 4) {
            int id = __ldg(&nidx[e]);
            float4 p = g_geom4[id];
            float dx = p.x - qx, dy = p.y - qy, dz = p.z - qz;
            float d2 = dx * dx + dy * dy + dz * dz;
            sd  += sqrtf(d2);
            sd2 += d2;
            sx += p.x; sy += p.y; sz += p.z;
            sxx += p.x * p.x; sxy += p.x * p.y; sxz += p.x * p.z;
            syy += p.y * p.y; syz += p.y * p.z; szz += p.z * p.z;
        }
    }

#pragma unroll
    for (int o = 1; o <= 2; o <<= 1) {
        sd  += __shfl_xor_sync(0xffffffffu, sd, o);
        sd2 += __shfl_xor_sync(0xffffffffu, sd2, o);
        sx  += __shfl_xor_sync(0xffffffffu, sx, o);
        sy  += __shfl_xor_sync(0xffffffffu, sy, o);
        sz  += __shfl_xor_sync(0xffffffffu, sz, o);
        sxx += __shfl_xor_sync(0xffffffffu, sxx, o);
        sxy += __shfl_xor_sync(0xffffffffu, sxy, o);
        sxz += __shfl_xor_sync(0xffffffffu, sxz, o);
        syy += __shfl_xor_sync(0xffffffffu, syy, o);
        syz += __shfl_xor_sync(0xffffffffu, syz, o);
        szz += __shfl_xor_sync(0xffffffffu, szz, o);
    }

    float f[FEAT];
#pragma unroll
    for (int i = 0; i < FEAT; i++) f[i] = 0.f;

    __shared__ float sf[64][10];
    int row = threadIdx.x >> 2;

    if (sub == 0) {
        if (valid && cnt > 0) {
            float fcnt = (float)cnt;
            float inv = 1.f / fmaxf(fcnt, 1.f);

            float davg = sd * inv;
            float ex2  = sd2 * inv;
            float dvar = fmaxf(ex2 - davg * davg, 0.f);

            float cx = sx * inv, cy = sy * inv, cz = sz * inv;

            float a = sxx * inv - cx * cx;
            float b = syy * inv - cy * cy;
            float c = szz * inv - cz * cz;
            float d = sxy * inv - cx * cy;
            float e = sxz * inv - cx * cz;
            float ff = syz * inv - cy * cz;

            float e1, e2, e3;
            float p1 = d * d + e * e + ff * ff;
            float qm = (a + b + c) * (1.f / 3.f);
            float aa = a - qm, bb = b - qm, cc = c - qm;
            float p2 = aa * aa + bb * bb + cc * cc + 2.f * p1;
            if (p2 <= 1e-22f) {
                e1 = e2 = e3 = qm;
            } else {
                float p = sqrtf(p2 * (1.f / 6.f));
                float ipv = 1.f / p;
                float b11 = aa * ipv, b22 = bb * ipv, b33 = cc * ipv;
                float b12 = d * ipv, b13 = e * ipv, b23 = ff * ipv;
                float r = 0.5f * (b11 * (b22 * b33 - b23 * b23)
                                - b12 * (b12 * b33 - b23 * b13)
                                + b13 * (b12 * b23 - b22 * b13));
                r = fminf(fmaxf(r, -1.f), 1.f);
                float phi = acosf(r) * (1.f / 3.f);
                e1 = qm + 2.f * p * __cosf(phi);
                e3 = qm + 2.f * p * __cosf(phi + 2.0943951023931953f);
                e2 = 3.f * qm - e1 - e3;
            }

            f[0] = fcnt; f[1] = davg; f[2] = dvar;
            f[3] = cx - qx; f[4] = cy - qy; f[5] = cz - qz;
            f[6] = e1; f[7] = e2; f[8] = e3;
        }
        if (valid) {
#pragma unroll
            for (int i = 0; i < FEAT; i++) g_feat[i * N_QUERY_MAX + q] = f[i];
        }
#pragma unroll
        for (int i = 0; i < FEAT; i++) sf[row][i] = f[i];
    }
    __syncthreads();

    int w = threadIdx.x >> 5, lane = threadIdx.x & 31;
    for (int c = w; c < FEAT; c += 8) {
        float a0 = sf[lane][c], a1 = sf[lane + 32][c];
        double s  = (double)a0 + (double)a1;
        double s2 = (double)a0 * a0 + (double)a1 * a1;
#pragma unroll
        for (int o = 16; o; o >>= 1) {
            s  += __shfl_xor_sync(0xffffffffu, s, o);
            s2 += __shfl_xor_sync(0xffffffffu, s2, o);
        }
        if (lane == 0) {
            atomicAdd(&g_sums[c], s);
            atomicAdd(&g_sums[FEAT + c], s2);
        }
    }
}

// ---------------- K3: MLP with mma.sync bf16 split layer 2 ----------------
// 128 queries/block, 256 threads (8 warps). Warp tile 32q x 64o.
// A' = [hi|lo] hA[128][136] bf16 (row stride 136 -> conflict-free frags)
// B' = [hi|lo] w2t[128][136] bf16 (W2 transposed, col-major frags)
// 3-term split over 12 k16-steps.
#define RS 136                 // bf16 row stride
#define RSB 272                // byte row stride
#define S_W1   0               // 2304 B
#define S_B1   2304            // 256
#define S_B2   2560            // 512
#define S_NRM  3072            // 128
#define S_HA   3200            // 128*272 = 34816
#define S_W2T  38016           // 34816
#define S_TOTAL 72832

__global__ __launch_bounds__(256)
void mlp_kernel(const float* __restrict__ gW1, const float* __restrict__ gb1,
                const float* __restrict__ gW2, const float* __restrict__ gb2,
                float* __restrict__ out, int Qn) {
    extern __shared__ char smem[];
    int tid = threadIdx.x;
    int wid = tid >> 5, lane = tid & 31;
    int qb = blockIdx.x * 128;

    // ---- phase 1: params + W2 transpose/split ----
    for (int i = tid; i < FEAT * HID; i += 256)
        *(float*)(smem + S_W1 + 4 * i) = gW1[i];
    if (tid < HID) *(float*)(smem + S_B1 + 4 * tid) = gb1[tid];
    if (tid < OUT) *(float*)(smem + S_B2 + 4 * tid) = gb2[tid];
    if (tid < FEAT) {
        double Qd = (double)Qn;
        double mean = g_sums[tid] / Qd;
        double var = (g_sums[FEAT + tid] - Qd * mean * mean) / (Qd - 1.0);
        if (var < 0.0) var = 0.0;
        double sd = sqrt(var);
        *(float*)(smem + S_NRM + 4 * tid) = (float)mean;
        *(float*)(smem + S_NRM + 4 * (FEAT + tid)) =
            (sd < 1e-6) ? 1.0f : (float)(1.0 / sd);
    }
#pragma unroll
    for (int it = 0; it < (HID * OUT) / 256; it++) {
        int idx = tid + it * 256;
        int k = idx >> 7, n = idx & 127;
        float v = gW2[idx];
        __nv_bfloat16 hi = __float2bfloat16(v);
        __nv_bfloat16 lo = __float2bfloat16(v - __bfloat162float(hi));
        *(__nv_bfloat16*)(smem + S_W2T + n * RSB + k * 2) = hi;
        *(__nv_bfloat16*)(smem + S_W2T + n * RSB + 128 + k * 2) = lo;
    }
    __syncthreads();

    // ---- phase 2: layer 1 (2 threads/query, 32 h each) -> hA hi/lo ----
    {
        int ql = tid & 127;
        int half = tid >> 7;           // 0 or 1 -> h outputs [half*32, +32)
        int q = qb + ql;
        int qc = (q < Qn) ? q : (Qn - 1);

        ull fnp[FEAT];
#pragma unroll
        for (int i = 0; i < FEAT; i++) {
            float mean = *(float*)(smem + S_NRM + 4 * i);
            float fac  = *(float*)(smem + S_NRM + 4 * (FEAT + i));
            float v = (g_feat[i * N_QUERY_MAX + qc] - mean) * fac;
            fnp[i] = pk2(v, v);
        }

        float h[32];
        int ob = half * 32;
#pragma unroll
        for (int op = 0; op < 16; op++) {
            int o = ob + 2 * op;
            ull acc = *(const ull*)(smem + S_B1 + 4 * o);
#pragma unroll
            for (int ffi = 0; ffi < FEAT; ffi++)
                acc = fma2(fnp[ffi], *(const ull*)(smem + S_W1 + 4 * (ffi * HID + o)), acc);
            float lo, hi; upk2(lo, hi, acc);
            h[2 * op]     = fmaxf(lo, 0.f);
            h[2 * op + 1] = fmaxf(hi, 0.f);
        }

        // split + pack
        uint32_t hiW[16], loW[16];
#pragma unroll
        for (int j = 0; j < 16; j++) {
            float v0 = h[2 * j], v1 = h[2 * j + 1];
            __nv_bfloat16 h0 = __float2bfloat16(v0);
            __nv_bfloat16 h1 = __float2bfloat16(v1);
            float r0 = v0 - __bfloat162float(h0);
            float r1 = v1 - __bfloat162float(h1);
            uint16_t u0, u1; memcpy(&u0, &h0, 2); memcpy(&u1, &h1, 2);
            hiW[j] = (uint32_t)u0 | ((uint32_t)u1 << 16);
            loW[j] = bf2pack(r0, r1);
        }
        // 4+4 STS.128: hi at [ql][half*32 + ...], lo at +128B
        char* rowp = smem + S_HA + ql * RSB + half * 64;
#pragma unroll
        for (int i = 0; i < 4; i++) {
            uint4 vh = make_uint4(hiW[4 * i], hiW[4 * i + 1], hiW[4 * i + 2], hiW[4 * i + 3]);
            uint4 vl = make_uint4(loW[4 * i], loW[4 * i + 1], loW[4 * i + 2], loW[4 * i + 3]);
            *(uint4*)(rowp + 16 * i) = vh;
            *(uint4*)(rowp + 128 + 16 * i) = vl;
        }
    }
    __syncthreads();

    // ---- phase 3: mma.sync layer 2 ----
    int wm = wid & 3;            // q group: rows [wm*32, wm*32+32)
    int wn = wid >> 2;           // o group: cols [wn*64, wn*64+64)
    int g = lane >> 2;           // 0..7
    int tq = lane & 3;           // 0..3

    // k-step segment tables (bf16 units within 136-stride rows)
    const int ks_a[12] = {0, 16, 32, 48, 64, 80, 96, 112, 0, 16, 32, 48};
    const int ks_b[12] = {0, 16, 32, 48, 0, 16, 32, 48, 64, 80, 96, 112};

    float acc[2][8][4];
#pragma unroll
    for (int nt = 0; nt < 8; nt++) {
        int col = wn * 64 + nt * 8 + 2 * tq;
        float c0 = *(float*)(smem + S_B2 + 4 * col);
        float c1 = *(float*)(smem + S_B2 + 4 * (col + 1));
#pragma unroll
        for (int mt = 0; mt < 2; mt++) {
            acc[mt][nt][0] = c0; acc[mt][nt][1] = c1;
            acc[mt][nt][2] = c0; acc[mt][nt][3] = c1;
        }
    }

    const char* haB = smem + S_HA;
    const char* wtB = smem + S_W2T;

#pragma unroll
    for (int s = 0; s < 12; s++) {
        int ka = ks_a[s], kb = ks_b[s];
        uint32_t afr[2][4];
#pragma unroll
        for (int mt = 0; mt < 2; mt++) {
            const char* ap = haB + (wm * 32 + mt * 16 + g) * RSB + (ka + 2 * tq) * 2;
            afr[mt][0] = *(const uint32_t*)(ap);
            afr[mt][2] = *(const uint32_t*)(ap + 16);
            afr[mt][1] = *(const uint32_t*)(ap + 8 * RSB);
            afr[mt][3] = *(const uint32_t*)(ap + 8 * RSB + 16);
        }
#pragma unroll
        for (int nt = 0; nt < 8; nt++) {
            const char* bp = wtB + (wn * 64 + nt * 8 + g) * RSB + (kb + 2 * tq) * 2;
            uint32_t b0 = *(const uint32_t*)(bp);
            uint32_t b1 = *(const uint32_t*)(bp + 16);
            mma16816(acc[0][nt], afr[0][0], afr[0][1], afr[0][2], afr[0][3], b0, b1);
            mma16816(acc[1][nt], afr[1][0], afr[1][1], afr[1][2], afr[1][3], b0, b1);
        }
    }

    // ---- epilogue: relu + direct float2 stores ----
#pragma unroll
    for (int mt = 0; mt < 2; mt++) {
        int gq0 = qb + wm * 32 + mt * 16 + g;
#pragma unroll
        for (int nt = 0; nt < 8; nt++) {
            int col = wn * 64 + nt * 8 + 2 * tq;
            if (gq0 < Qn) {
                float2 r0;
                r0.x = fmaxf(acc[mt][nt][0], 0.f);
                r0.y = fmaxf(acc[mt][nt][1], 0.f);
                *(float2*)&out[(size_t)gq0 * OUT + col] = r0;
            }
            if (gq0 + 8 < Qn) {
                float2 r1;
                r1.x = fmaxf(acc[mt][nt][2], 0.f);
                r1.y = fmaxf(acc[mt][nt][3], 0.f);
                *(float2*)&out[(size_t)(gq0 + 8) * OUT + col] = r1;
            }
        }
    }
}

// ---------------- launch ----------------
// Launch order: prep(0), moments(1), dummy(2), mlp(3) -> ncu profiles mlp.
extern "C" void kernel_launch(void* const* d_in, const int* in_sizes, int n_in,
                              void* d_out, int out_size) {
    const float* geom = (const float*)d_in[0];
    const float* lq   = (const float*)d_in[1];
    const int*   nidx = (const int*)d_in[2];
    const int*   rs   = (const int*)d_in[3];
    const float* W1   = (const float*)d_in[4];
    const float* b1   = (const float*)d_in[5];
    const float* W2   = (const float*)d_in[6];
    const float* b2   = (const float*)d_in[7];
    float* out = (float*)d_out;

    int nnodes = in_sizes[0] / 3;
    int Qn = in_sizes[3] - 1;

    prep_kernel<<<(nnodes + 255) / 256, 256>>>(geom, nnodes);
    moments_feat_kernel<<<((long long)Qn * 4 + 255) / 256, 256>>>(lq, nidx, rs, Qn);
    dummy_kernel<<<1, 32>>>();

    cudaFuncSetAttribute(mlp_kernel, cudaFuncAttributeMaxDynamicSharedMemorySize, S_TOTAL);
    mlp_kernel<<<(Qn + 127) / 128, 256, S_TOTAL>>>(W1, b1, W2, b2, out, Qn);
}

// round 15
// speedup vs baseline: 1.1475x; 1.1475x over previous
#include <cuda_runtime.h>
#include <cuda_bf16.h>
#include <math.h>
#include <cstdint>

#define N_NODES_MAX 200000
#define N_QUERY_MAX 131072
#define FEAT 9
#define HID 64
#define OUT 128

typedef unsigned long long ull;

// ---------------- static device scratch ----------------
__device__ float4 g_geom4[N_NODES_MAX];
__device__ float  g_feat[FEAT * N_QUERY_MAX];   // column-major [FEAT][Q]
__device__ double g_sums[2 * FEAT];

// ---------------- f32x2 helpers ----------------
__device__ __forceinline__ ull pk2(float lo, float hi) {
    ull r; asm("mov.b64 %0,{%1,%2};" : "=l"(r) : "f"(lo), "f"(hi)); return r;
}
__device__ __forceinline__ void upk2(float& lo, float& hi, ull v) {
    asm("mov.b64 {%0,%1},%2;" : "=f"(lo), "=f"(hi) : "l"(v));
}
__device__ __forceinline__ ull fma2(ull a, ull b, ull c) {
    ull d; asm("fma.rn.f32x2 %0,%1,%2,%3;" : "=l"(d) : "l"(a), "l"(b), "l"(c));
    return d;
}

// bf16 mma (arch-generic PTX, works on compute_103)
__device__ __forceinline__ void mma16816(float* d,
                                         uint32_t a0, uint32_t a1, uint32_t a2, uint32_t a3,
                                         uint32_t b0, uint32_t b1) {
    asm volatile(
        "mma.sync.aligned.m16n8k16.row.col.f32.bf16.bf16.f32 "
        "{%0,%1,%2,%3},{%4,%5,%6,%7},{%8,%9},{%0,%1,%2,%3};"
        : "+f"(d[0]), "+f"(d[1]), "+f"(d[2]), "+f"(d[3])
        : "r"(a0), "r"(a1), "r"(a2), "r"(a3), "r"(b0), "r"(b1));
}

__device__ __forceinline__ uint32_t bf2pack(float v0, float v1) {
    __nv_bfloat16 b0 = __float2bfloat16(v0);
    __nv_bfloat16 b1 = __float2bfloat16(v1);
    uint16_t u0, u1;
    memcpy(&u0, &b0, 2); memcpy(&u1, &b1, 2);
    return (uint32_t)u0 | ((uint32_t)u1 << 16);
}

// ---------------- K1: pad geometry + zero accumulators ----------------
__global__ void prep_kernel(const float* __restrict__ geom, int n) {
    int i = blockIdx.x * blockDim.x + threadIdx.x;
    if (blockIdx.x == 0 && threadIdx.x < 2 * FEAT) g_sums[threadIdx.x] = 0.0;
    if (i < n) {
        float4 p;
        p.x = geom[3 * i + 0];
        p.y = geom[3 * i + 1];
        p.z = geom[3 * i + 2];
        p.w = 0.f;
        g_geom4[i] = p;
    }
}

__global__ void dummy_kernel() {}

// ---------------- K2: moments + features, 4 threads per query (R10 best) ----------------
__global__ __launch_bounds__(256)
void moments_feat_kernel(const float* __restrict__ lq,
                         const int* __restrict__ nidx,
                         const int* __restrict__ rs,
                         int Qn) {
    int t = blockIdx.x * blockDim.x + threadIdx.x;
    int q = t >> 2;
    int sub = t & 3;
    bool valid = (q < Qn);
    int qc = valid ? q : (Qn - 1);

    int start = rs[qc];
    int end   = rs[qc + 1];
    int cnt   = end - start;

    float qx = __ldg(&lq[3 * qc + 0]);
    float qy = __ldg(&lq[3 * qc + 1]);
    float qz = __ldg(&lq[3 * qc + 2]);

    float sd = 0.f, sd2 = 0.f;
    float sx = 0.f, sy = 0.f, sz = 0.f;
    float sxx = 0.f, sxy = 0.f, sxz = 0.f, syy = 0.f, syz = 0.f, szz = 0.f;

    if (cnt == 32 && (start & 3) == 0) {
        const int4* ip = (const int4*)(nidx + start) + sub * 2;
        int4 a = __ldg(ip), b = __ldg(ip + 1);
        int idf[8] = {a.x, a.y, a.z, a.w, b.x, b.y, b.z, b.w};
#pragma unroll
        for (int e = 0; e < 8; e++) {
            float4 p = g_geom4[idf[e]];
            float dx = p.x - qx, dy = p.y - qy, dz = p.z - qz;
            float d2 = dx * dx + dy * dy + dz * dz;
            sd  += sqrtf(d2);
            sd2 += d2;
            sx += p.x; sy += p.y; sz += p.z;
            sxx += p.x * p.x; sxy += p.x * p.y; sxz += p.x * p.z;
            syy += p.y * p.y; syz += p.y * p.z; szz += p.z * p.z;
        }
    } else {
        for (int e = start + sub; e < end; e += 4) {
            int id = __ldg(&nidx[e]);
            float4 p = g_geom4[id];
            float dx = p.x - qx, dy = p.y - qy, dz = p.z - qz;
            float d2 = dx * dx + dy * dy + dz * dz;
            sd  += sqrtf(d2);
            sd2 += d2;
            sx += p.x; sy += p.y; sz += p.z;
            sxx += p.x * p.x; sxy += p.x * p.y; sxz += p.x * p.z;
            syy += p.y * p.y; syz += p.y * p.z; szz += p.z * p.z;
        }
    }

#pragma unroll
    for (int o = 1; o <= 2; o <<= 1) {
        sd  += __shfl_xor_sync(0xffffffffu, sd, o);
        sd2 += __shfl_xor_sync(0xffffffffu, sd2, o);
        sx  += __shfl_xor_sync(0xffffffffu, sx, o);
        sy  += __shfl_xor_sync(0xffffffffu, sy, o);
        sz  += __shfl_xor_sync(0xffffffffu, sz, o);
        sxx += __shfl_xor_sync(0xffffffffu, sxx, o);
        sxy += __shfl_xor_sync(0xffffffffu, sxy, o);
        sxz += __shfl_xor_sync(0xffffffffu, sxz, o);
        syy += __shfl_xor_sync(0xffffffffu, syy, o);
        syz += __shfl_xor_sync(0xffffffffu, syz, o);
        szz += __shfl_xor_sync(0xffffffffu, szz, o);
    }

    float f[FEAT];
#pragma unroll
    for (int i = 0; i < FEAT; i++) f[i] = 0.f;

    __shared__ float sf[64][10];
    int row = threadIdx.x >> 2;

    if (sub == 0) {
        if (valid && cnt > 0) {
            float fcnt = (float)cnt;
            float inv = 1.f / fmaxf(fcnt, 1.f);

            float davg = sd * inv;
            float ex2  = sd2 * inv;
            float dvar = fmaxf(ex2 - davg * davg, 0.f);

            float cx = sx * inv, cy = sy * inv, cz = sz * inv;

            float a = sxx * inv - cx * cx;
            float b = syy * inv - cy * cy;
            float c = szz * inv - cz * cz;
            float d = sxy * inv - cx * cy;
            float e = sxz * inv - cx * cz;
            float ff = syz * inv - cy * cz;

            float e1, e2, e3;
            float p1 = d * d + e * e + ff * ff;
            float qm = (a + b + c) * (1.f / 3.f);
            float aa = a - qm, bb = b - qm, cc = c - qm;
            float p2 = aa * aa + bb * bb + cc * cc + 2.f * p1;
            if (p2 <= 1e-22f) {
                e1 = e2 = e3 = qm;
            } else {
                float p = sqrtf(p2 * (1.f / 6.f));
                float ipv = 1.f / p;
                float b11 = aa * ipv, b22 = bb * ipv, b33 = cc * ipv;
                float b12 = d * ipv, b13 = e * ipv, b23 = ff * ipv;
                float r = 0.5f * (b11 * (b22 * b33 - b23 * b23)
                                - b12 * (b12 * b33 - b23 * b13)
                                + b13 * (b12 * b23 - b22 * b13));
                r = fminf(fmaxf(r, -1.f), 1.f);
                float phi = acosf(r) * (1.f / 3.f);
                e1 = qm + 2.f * p * __cosf(phi);
                e3 = qm + 2.f * p * __cosf(phi + 2.0943951023931953f);
                e2 = 3.f * qm - e1 - e3;
            }

            f[0] = fcnt; f[1] = davg; f[2] = dvar;
            f[3] = cx - qx; f[4] = cy - qy; f[5] = cz - qz;
            f[6] = e1; f[7] = e2; f[8] = e3;
        }
        if (valid) {
#pragma unroll
            for (int i = 0; i < FEAT; i++) g_feat[i * N_QUERY_MAX + q] = f[i];
        }
#pragma unroll
        for (int i = 0; i < FEAT; i++) sf[row][i] = f[i];
    }
    __syncthreads();

    int w = threadIdx.x >> 5, lane = threadIdx.x & 31;
    for (int c = w; c < FEAT; c += 8) {
        float a0 = sf[lane][c], a1 = sf[lane + 32][c];
        double s  = (double)a0 + (double)a1;
        double s2 = (double)a0 * a0 + (double)a1 * a1;
#pragma unroll
        for (int o = 16; o; o >>= 1) {
            s  += __shfl_xor_sync(0xffffffffu, s, o);
            s2 += __shfl_xor_sync(0xffffffffu, s2, o);
        }
        if (lane == 0) {
            atomicAdd(&g_sums[c], s);
            atomicAdd(&g_sums[FEAT + c], s2);
        }
    }
}

// ---------------- K3: MLP with mma.sync bf16 split layer 2 (o-chunked) ----------------
// 128 queries/block, 256 threads (8 warps). Warp tile 32q x 64o processed as
// TWO sequential 32-col chunks -> live acc halves (32 regs) -> 2 blocks/SM.
#define RS 136                 // bf16 row stride
#define RSB 272                // byte row stride
#define S_W1   0               // 2304 B
#define S_B1   2304            // 256
#define S_B2   2560            // 512
#define S_NRM  3072            // 128
#define S_HA   3200            // 128*272 = 34816
#define S_W2T  38016           // 34816
#define S_TOTAL 72832

__global__ __launch_bounds__(256, 2)
void mlp_kernel(const float* __restrict__ gW1, const float* __restrict__ gb1,
                const float* __restrict__ gW2, const float* __restrict__ gb2,
                float* __restrict__ out, int Qn) {
    extern __shared__ char smem[];
    int tid = threadIdx.x;
    int wid = tid >> 5, lane = tid & 31;
    int qb = blockIdx.x * 128;

    // ---- phase 1: params + W2 transpose/split ----
    for (int i = tid; i < FEAT * HID; i += 256)
        *(float*)(smem + S_W1 + 4 * i) = gW1[i];
    if (tid < HID) *(float*)(smem + S_B1 + 4 * tid) = gb1[tid];
    if (tid < OUT) *(float*)(smem + S_B2 + 4 * tid) = gb2[tid];
    if (tid < FEAT) {
        double Qd = (double)Qn;
        double mean = g_sums[tid] / Qd;
        double var = (g_sums[FEAT + tid] - Qd * mean * mean) / (Qd - 1.0);
        if (var < 0.0) var = 0.0;
        double sd = sqrt(var);
        *(float*)(smem + S_NRM + 4 * tid) = (float)mean;
        *(float*)(smem + S_NRM + 4 * (FEAT + tid)) =
            (sd < 1e-6) ? 1.0f : (float)(1.0 / sd);
    }
#pragma unroll
    for (int it = 0; it < (HID * OUT) / 256; it++) {
        int idx = tid + it * 256;
        int k = idx >> 7, n = idx & 127;
        float v = gW2[idx];
        __nv_bfloat16 hi = __float2bfloat16(v);
        __nv_bfloat16 lo = __float2bfloat16(v - __bfloat162float(hi));
        *(__nv_bfloat16*)(smem + S_W2T + n * RSB + k * 2) = hi;
        *(__nv_bfloat16*)(smem + S_W2T + n * RSB + 128 + k * 2) = lo;
    }
    __syncthreads();

    // ---- phase 2: layer 1 (2 threads/query, 32 h each) -> hA hi/lo ----
    {
        int ql = tid & 127;
        int half = tid >> 7;           // 0 or 1 -> h outputs [half*32, +32)
        int q = qb + ql;
        int qc = (q < Qn) ? q : (Qn - 1);

        ull fnp[FEAT];
#pragma unroll
        for (int i = 0; i < FEAT; i++) {
            float mean = *(float*)(smem + S_NRM + 4 * i);
            float fac  = *(float*)(smem + S_NRM + 4 * (FEAT + i));
            float v = (g_feat[i * N_QUERY_MAX + qc] - mean) * fac;
            fnp[i] = pk2(v, v);
        }

        float h[32];
        int ob = half * 32;
#pragma unroll
        for (int op = 0; op < 16; op++) {
            int o = ob + 2 * op;
            ull acc = *(const ull*)(smem + S_B1 + 4 * o);
#pragma unroll
            for (int ffi = 0; ffi < FEAT; ffi++)
                acc = fma2(fnp[ffi], *(const ull*)(smem + S_W1 + 4 * (ffi * HID + o)), acc);
            float lo, hi; upk2(lo, hi, acc);
            h[2 * op]     = fmaxf(lo, 0.f);
            h[2 * op + 1] = fmaxf(hi, 0.f);
        }

        uint32_t hiW[16], loW[16];
#pragma unroll
        for (int j = 0; j < 16; j++) {
            float v0 = h[2 * j], v1 = h[2 * j + 1];
            __nv_bfloat16 h0 = __float2bfloat16(v0);
            __nv_bfloat16 h1 = __float2bfloat16(v1);
            float r0 = v0 - __bfloat162float(h0);
            float r1 = v1 - __bfloat162float(h1);
            uint16_t u0, u1; memcpy(&u0, &h0, 2); memcpy(&u1, &h1, 2);
            hiW[j] = (uint32_t)u0 | ((uint32_t)u1 << 16);
            loW[j] = bf2pack(r0, r1);
        }
        char* rowp = smem + S_HA + ql * RSB + half * 64;
#pragma unroll
        for (int i = 0; i < 4; i++) {
            uint4 vh = make_uint4(hiW[4 * i], hiW[4 * i + 1], hiW[4 * i + 2], hiW[4 * i + 3]);
            uint4 vl = make_uint4(loW[4 * i], loW[4 * i + 1], loW[4 * i + 2], loW[4 * i + 3]);
            *(uint4*)(rowp + 16 * i) = vh;
            *(uint4*)(rowp + 128 + 16 * i) = vl;
        }
    }
    __syncthreads();

    // ---- phase 3: mma.sync layer 2, o-chunked ----
    int wm = wid & 3;            // q group: rows [wm*32, wm*32+32)
    int wn = wid >> 2;           // o group: cols [wn*64, wn*64+64)
    int g = lane >> 2;           // 0..7
    int tq = lane & 3;           // 0..3

    const int ks_a[12] = {0, 16, 32, 48, 64, 80, 96, 112, 0, 16, 32, 48};
    const int ks_b[12] = {0, 16, 32, 48, 0, 16, 32, 48, 64, 80, 96, 112};

    const char* haB = smem + S_HA;
    const char* wtB = smem + S_W2T;

#pragma unroll 1
    for (int oc = 0; oc < 2; oc++) {
        int col0 = wn * 64 + oc * 32;

        float acc[2][4][4];
#pragma unroll
        for (int nt = 0; nt < 4; nt++) {
            int col = col0 + nt * 8 + 2 * tq;
            float c0 = *(float*)(smem + S_B2 + 4 * col);
            float c1 = *(float*)(smem + S_B2 + 4 * (col + 1));
#pragma unroll
            for (int mt = 0; mt < 2; mt++) {
                acc[mt][nt][0] = c0; acc[mt][nt][1] = c1;
                acc[mt][nt][2] = c0; acc[mt][nt][3] = c1;
            }
        }

#pragma unroll
        for (int s = 0; s < 12; s++) {
            int ka = ks_a[s], kb = ks_b[s];
            uint32_t afr[2][4];
#pragma unroll
            for (int mt = 0; mt < 2; mt++) {
                const char* ap = haB + (wm * 32 + mt * 16 + g) * RSB + (ka + 2 * tq) * 2;
                afr[mt][0] = *(const uint32_t*)(ap);
                afr[mt][2] = *(const uint32_t*)(ap + 16);
                afr[mt][1] = *(const uint32_t*)(ap + 8 * RSB);
                afr[mt][3] = *(const uint32_t*)(ap + 8 * RSB + 16);
            }
#pragma unroll
            for (int nt = 0; nt < 4; nt++) {
                const char* bp = wtB + (col0 + nt * 8 + g) * RSB + (kb + 2 * tq) * 2;
                uint32_t b0 = *(const uint32_t*)(bp);
                uint32_t b1 = *(const uint32_t*)(bp + 16);
                mma16816(acc[0][nt], afr[0][0], afr[0][1], afr[0][2], afr[0][3], b0, b1);
                mma16816(acc[1][nt], afr[1][0], afr[1][1], afr[1][2], afr[1][3], b0, b1);
            }
        }

        // epilogue for this chunk: relu + float2 stores
#pragma unroll
        for (int mt = 0; mt < 2; mt++) {
            int gq0 = qb + wm * 32 + mt * 16 + g;
#pragma unroll
            for (int nt = 0; nt < 4; nt++) {
                int col = col0 + nt * 8 + 2 * tq;
                if (gq0 < Qn) {
                    float2 r0;
                    r0.x = fmaxf(acc[mt][nt][0], 0.f);
                    r0.y = fmaxf(acc[mt][nt][1], 0.f);
                    *(float2*)&out[(size_t)gq0 * OUT + col] = r0;
                }
                if (gq0 + 8 < Qn) {
                    float2 r1;
                    r1.x = fmaxf(acc[mt][nt][2], 0.f);
                    r1.y = fmaxf(acc[mt][nt][3], 0.f);
                    *(float2*)&out[(size_t)(gq0 + 8) * OUT + col] = r1;
                }
            }
        }
    }
}

// ---------------- launch ----------------
// Launch order: prep(0), moments(1), dummy(2), mlp(3) -> ncu profiles mlp.
extern "C" void kernel_launch(void* const* d_in, const int* in_sizes, int n_in,
                              void* d_out, int out_size) {
    const float* geom = (const float*)d_in[0];
    const float* lq   = (const float*)d_in[1];
    const int*   nidx = (const int*)d_in[2];
    const int*   rs   = (const int*)d_in[3];
    const float* W1   = (const float*)d_in[4];
    const float* b1   = (const float*)d_in[5];
    const float* W2   = (const float*)d_in[6];
    const float* b2   = (const float*)d_in[7];
    float* out = (float*)d_out;

    int nnodes = in_sizes[0] / 3;
    int Qn = in_sizes[3] - 1;

    prep_kernel<<<(nnodes + 255) / 256, 256>>>(geom, nnodes);
    moments_feat_kernel<<<((long long)Qn * 4 + 255) / 256, 256>>>(lq, nidx, rs, Qn);
    dummy_kernel<<<1, 32>>>();

    cudaFuncSetAttribute(mlp_kernel, cudaFuncAttributeMaxDynamicSharedMemorySize, S_TOTAL);
    mlp_kernel<<<(Qn + 127) / 128, 256, S_TOTAL>>>(W1, b1, W2, b2, out, Qn);
}